// round 4
// baseline (speedup 1.0000x reference)
#include <cuda_runtime.h>
#include <cstdint>

// ---------------- problem constants ----------------
#define N_ATOMS 100000
#define DIN     120
#define HID     128
#define NMOL    2000
#define TILE    64                  // atoms per CTA (= M)
#define NTHR    128                 // 4 warps
#define NBLK    1566
#define PTOT    (NBLK * TILE)       // 100224 >= 100000 + 3*63

#define LDX     132                 // padded row stride (floats) for all smem tiles

// ---------------- device scratch ----------------
__device__ float g_flat_d[N_ATOMS * DIN];   // dE/dfp
__device__ int   perm_d[PTOT];
__device__ int   counts_d[3];
__device__ int   cursor_d[3];

__device__ __forceinline__ int elem_of(int z) {
    return (z == 1) ? 0 : ((z == 6) ? 1 : 2);
}

__device__ __forceinline__ float tf32r(float x) {
    uint32_t u;
    asm("cvt.rna.tf32.f32 %0, %1;" : "=r"(u) : "f"(x));
    return __uint_as_float(u);
}
__device__ __forceinline__ uint32_t f2b(float f) { return __float_as_uint(f); }

__device__ __forceinline__ void mma_tf32(
    float& d0, float& d1, float& d2, float& d3,
    uint32_t a0, uint32_t a1, uint32_t a2, uint32_t a3,
    uint32_t b0, uint32_t b1)
{
    asm volatile(
        "mma.sync.aligned.m16n8k8.row.col.f32.tf32.tf32.f32 "
        "{%0,%1,%2,%3}, {%4,%5,%6,%7}, {%8,%9}, {%0,%1,%2,%3};"
        : "+f"(d0), "+f"(d1), "+f"(d2), "+f"(d3)
        : "r"(a0), "r"(a1), "r"(a2), "r"(a3), "r"(b0), "r"(b1));
}

__device__ __forceinline__ float fast_tanh(float x) {
    x = fminf(15.f, fmaxf(-15.f, x));
    float e = __expf(2.f * x);
    return __fdividef(e - 1.f, e + 1.f);
}

// ---------------- prelude kernels ----------------
__global__ void k_init(float* __restrict__ out) {
    int i = blockIdx.x * blockDim.x + threadIdx.x;
    if (i < NMOL + 3 * N_ATOMS) out[i] = 0.f;
    if (i < PTOT) perm_d[i] = -1;
    if (i < 3) { counts_d[i] = 0; cursor_d[i] = 0; }
}

__global__ void k_count(const int* __restrict__ z) {
    __shared__ int loc[3];
    int t = threadIdx.x;
    if (t < 3) loc[t] = 0;
    __syncthreads();
    int i = blockIdx.x * blockDim.x + t;
    if (i < N_ATOMS) atomicAdd(&loc[elem_of(z[i])], 1);
    __syncthreads();
    if (t < 3 && loc[t] > 0) atomicAdd(&counts_d[t], loc[t]);
}

__global__ void k_offsets() {
    int r0 = (counts_d[0] + TILE - 1) / TILE * TILE;
    int r1 = (counts_d[1] + TILE - 1) / TILE * TILE;
    cursor_d[0] = 0;
    cursor_d[1] = r0;
    cursor_d[2] = r0 + r1;
}

__global__ void k_build(const int* __restrict__ z) {
    __shared__ int loc[3], base[3];
    int t = threadIdx.x;
    if (t < 3) loc[t] = 0;
    __syncthreads();
    int i = blockIdx.x * blockDim.x + t;
    int e = -1, r = 0;
    if (i < N_ATOMS) { e = elem_of(z[i]); r = atomicAdd(&loc[e], 1); }
    __syncthreads();
    if (t < 3) base[t] = (loc[t] > 0) ? atomicAdd(&cursor_d[t], loc[t]) : 0;
    __syncthreads();
    if (i < N_ATOMS) {
        int p = base[e] + r;
        if (p >= 0 && p < PTOT) perm_d[p] = i;
    }
}

// ---------------- weight staging ----------------
// Forward:  B[n][k] = W[k][n]  (mma .col B is k-contiguous => need W transposed)
__device__ __forceinline__ void stage_wf(float* __restrict__ Ws,
                                         const float* __restrict__ W,
                                         int Krows, int tid) {
    for (int idx = tid; idx < HID * HID; idx += NTHR) {
        int k = idx >> 7, n = idx & 127;
        float v = (k < Krows) ? __ldg(W + k * HID + n) : 0.f;
        Ws[n * LDX + k] = tf32r(v);
    }
}
// Backward: B[n][k] = W[n][k]  (native row-major)
__device__ __forceinline__ void stage_wn(float* __restrict__ Ws,
                                         const float* __restrict__ W,
                                         int Nrows, int tid) {
    for (int idx = tid; idx < HID * HID; idx += NTHR) {
        int n = idx >> 7, k = idx & 127;
        float v = (n < Nrows) ? __ldg(W + n * HID + k) : 0.f;
        Ws[n * LDX + k] = tf32r(v);
    }
}

// ---------------- warp-tiled GEMM: C[64x32 slice] += A[64x128] * B ----------
__device__ __forceinline__ void gemm64(
    const float* __restrict__ As, const float* __restrict__ Bs,
    int warp, int g, int q, float C[4][4][4])
{
#pragma unroll
    for (int mt = 0; mt < 4; mt++)
#pragma unroll
        for (int nt = 0; nt < 4; nt++)
#pragma unroll
            for (int i = 0; i < 4; i++) C[mt][nt][i] = 0.f;

#pragma unroll 4
    for (int kk = 0; kk < 16; kk++) {
        int kb = kk * 8 + q;
        uint32_t a[4][4];
#pragma unroll
        for (int mt = 0; mt < 4; mt++) {
            const float* ap = As + (16 * mt + g) * LDX + kb;
            a[mt][0] = f2b(ap[0]);
            a[mt][1] = f2b(ap[8 * LDX]);
            a[mt][2] = f2b(ap[4]);
            a[mt][3] = f2b(ap[8 * LDX + 4]);
        }
#pragma unroll
        for (int nt = 0; nt < 4; nt++) {
            const float* bp = Bs + (warp * 32 + nt * 8 + g) * LDX + kb;
            uint32_t b0 = f2b(bp[0]), b1 = f2b(bp[4]);
#pragma unroll
            for (int mt = 0; mt < 4; mt++)
                mma_tf32(C[mt][nt][0], C[mt][nt][1], C[mt][nt][2], C[mt][nt][3],
                         a[mt][0], a[mt][1], a[mt][2], a[mt][3], b0, b1);
        }
    }
}

// ---------------- fused MLP fwd+bwd (tf32 mma.sync) ----------------
// dyn smem: Xa[64*132] | H1[64*132] | H2[64*132] | Ws[128*132]
#define SMEM_DYN ((3 * TILE * LDX + HID * LDX) * 4)

__global__ __launch_bounds__(NTHR) void k_mlp(
    const int* __restrict__ z, const float* __restrict__ fp,
    const int* __restrict__ img,
    const float* __restrict__ W1, const float* __restrict__ b1,
    const float* __restrict__ W2, const float* __restrict__ b2,
    const float* __restrict__ W3, const float* __restrict__ b3,
    const float* __restrict__ W4, const float* __restrict__ b4,
    float* __restrict__ energy)
{
    extern __shared__ float sm[];
    float* Xa = sm;                        // activations / grads, in place
    float* H1 = Xa + TILE * LDX;           // exact h1
    float* H2 = H1 + TILE * LDX;           // exact h2
    float* Ws = H2 + TILE * LDX;           // staged weights [128][LDX]

    __shared__ int   s_aid[TILE];
    __shared__ int   s_e;
    __shared__ float e_s[TILE];

    int tid = threadIdx.x;
    int warp = tid >> 5, lane = tid & 31;
    int g = lane >> 2, q = lane & 3;

    if (tid == 0) s_e = -1;
    __syncthreads();
    if (tid < TILE) {
        int a = perm_d[blockIdx.x * TILE + tid];
        s_aid[tid] = a;
        e_s[tid] = 0.f;
        if (a >= 0) s_e = elem_of(__ldg(z + a));
    }
    __syncthreads();
    if (s_e < 0) return;
    int e = s_e;

    const float* W1e = W1 + e * DIN * HID;
    const float* W2e = W2 + e * HID * HID;
    const float* W3e = W3 + e * HID * HID;
    const float* W4e = W4 + e * HID;
    const float* b1e = b1 + e * HID;
    const float* b2e = b2 + e * HID;
    const float* b3e = b3 + e * HID;
    float        b4e = __ldg(b4 + e);

    // stage X (tf32-rounded, zero-padded) and W1^T
    for (int idx = tid; idx < TILE * HID; idx += NTHR) {
        int m = idx >> 7, k = idx & 127;
        int aid = s_aid[m];
        float v = (aid >= 0 && k < DIN) ? __ldg(fp + aid * DIN + k) : 0.f;
        Xa[m * LDX + k] = tf32r(v);
    }
    stage_wf(Ws, W1e, DIN, tid);
    __syncthreads();

    float C[4][4][4];

    // ================= Pass 1: h1 = tanh(X @ W1 + b1) =================
    gemm64(Xa, Ws, warp, g, q, C);
    __syncthreads();
#pragma unroll
    for (int mt = 0; mt < 4; mt++) {
        int r0 = 16 * mt + g, r1 = r0 + 8;
#pragma unroll
        for (int nt = 0; nt < 4; nt++) {
            int col = warp * 32 + nt * 8 + 2 * q;
#pragma unroll
            for (int i = 0; i < 2; i++) {
                float h = fast_tanh(C[mt][nt][i] + __ldg(b1e + col + i));
                H1[r0 * LDX + col + i] = h;
                Xa[r0 * LDX + col + i] = tf32r(h);
                h = fast_tanh(C[mt][nt][2 + i] + __ldg(b1e + col + i));
                H1[r1 * LDX + col + i] = h;
                Xa[r1 * LDX + col + i] = tf32r(h);
            }
        }
    }
    stage_wf(Ws, W2e, HID, tid);
    __syncthreads();

    // ================= Pass 2: h2 = tanh(h1 @ W2 + b2) =================
    gemm64(Xa, Ws, warp, g, q, C);
    __syncthreads();
#pragma unroll
    for (int mt = 0; mt < 4; mt++) {
        int r0 = 16 * mt + g, r1 = r0 + 8;
#pragma unroll
        for (int nt = 0; nt < 4; nt++) {
            int col = warp * 32 + nt * 8 + 2 * q;
#pragma unroll
            for (int i = 0; i < 2; i++) {
                float h = fast_tanh(C[mt][nt][i] + __ldg(b2e + col + i));
                H2[r0 * LDX + col + i] = h;
                Xa[r0 * LDX + col + i] = tf32r(h);
                h = fast_tanh(C[mt][nt][2 + i] + __ldg(b2e + col + i));
                H2[r1 * LDX + col + i] = h;
                Xa[r1 * LDX + col + i] = tf32r(h);
            }
        }
    }
    stage_wf(Ws, W3e, HID, tid);
    __syncthreads();

    // ===== Pass 3: h3 = tanh(h2 @ W3 + b3); energy; dp3 = W4*(1-h3^2) =====
    gemm64(Xa, Ws, warp, g, q, C);
    __syncthreads();
#pragma unroll
    for (int mt = 0; mt < 4; mt++) {
        int r0 = 16 * mt + g, r1 = r0 + 8;
        float e0 = 0.f, e1 = 0.f;
#pragma unroll
        for (int nt = 0; nt < 4; nt++) {
            int col = warp * 32 + nt * 8 + 2 * q;
#pragma unroll
            for (int i = 0; i < 2; i++) {
                float w4 = __ldg(W4e + col + i);
                float bb = __ldg(b3e + col + i);
                float h = fast_tanh(C[mt][nt][i] + bb);
                e0 += h * w4;
                Xa[r0 * LDX + col + i] = tf32r(w4 * (1.f - h * h));
                h = fast_tanh(C[mt][nt][2 + i] + bb);
                e1 += h * w4;
                Xa[r1 * LDX + col + i] = tf32r(w4 * (1.f - h * h));
            }
        }
        e0 += __shfl_xor_sync(0xffffffffu, e0, 1);
        e0 += __shfl_xor_sync(0xffffffffu, e0, 2);
        e1 += __shfl_xor_sync(0xffffffffu, e1, 1);
        e1 += __shfl_xor_sync(0xffffffffu, e1, 2);
        if (q == 0) {
            atomicAdd(&e_s[r0], e0);
            atomicAdd(&e_s[r1], e1);
        }
    }
    stage_wn(Ws, W3e, HID, tid);
    __syncthreads();

    // scatter per-atom energies (e_s complete after the sync above)
    if (tid < TILE) {
        int aid = s_aid[tid];
        if (aid >= 0)
            atomicAdd(&energy[__ldg(img + aid)], e_s[tid] + b4e);
    }

    // ================= Pass 4: dp2 = (dp3 @ W3^T) * (1 - h2^2) =================
    gemm64(Xa, Ws, warp, g, q, C);
    __syncthreads();
#pragma unroll
    for (int mt = 0; mt < 4; mt++) {
        int r0 = 16 * mt + g, r1 = r0 + 8;
#pragma unroll
        for (int nt = 0; nt < 4; nt++) {
            int col = warp * 32 + nt * 8 + 2 * q;
#pragma unroll
            for (int i = 0; i < 2; i++) {
                float h = H2[r0 * LDX + col + i];
                Xa[r0 * LDX + col + i] = tf32r(C[mt][nt][i] * (1.f - h * h));
                h = H2[r1 * LDX + col + i];
                Xa[r1 * LDX + col + i] = tf32r(C[mt][nt][2 + i] * (1.f - h * h));
            }
        }
    }
    stage_wn(Ws, W2e, HID, tid);
    __syncthreads();

    // ================= Pass 5: dp1 = (dp2 @ W2^T) * (1 - h1^2) =================
    gemm64(Xa, Ws, warp, g, q, C);
    __syncthreads();
#pragma unroll
    for (int mt = 0; mt < 4; mt++) {
        int r0 = 16 * mt + g, r1 = r0 + 8;
#pragma unroll
        for (int nt = 0; nt < 4; nt++) {
            int col = warp * 32 + nt * 8 + 2 * q;
#pragma unroll
            for (int i = 0; i < 2; i++) {
                float h = H1[r0 * LDX + col + i];
                Xa[r0 * LDX + col + i] = tf32r(C[mt][nt][i] * (1.f - h * h));
                h = H1[r1 * LDX + col + i];
                Xa[r1 * LDX + col + i] = tf32r(C[mt][nt][2 + i] * (1.f - h * h));
            }
        }
    }
    stage_wn(Ws, W1e, DIN, tid);
    __syncthreads();

    // ================= Pass 6: g = dp1 @ W1^T  (cols 0..119) =================
    gemm64(Xa, Ws, warp, g, q, C);
    // no smem writes — store straight to global
#pragma unroll
    for (int mt = 0; mt < 4; mt++) {
        int r0 = 16 * mt + g, r1 = r0 + 8;
        int aid0 = s_aid[r0], aid1 = s_aid[r1];
#pragma unroll
        for (int nt = 0; nt < 4; nt++) {
            int col = warp * 32 + nt * 8 + 2 * q;
            if (col < DIN) {
                if (aid0 >= 0)
                    *reinterpret_cast<float2*>(g_flat_d + aid0 * DIN + col) =
                        make_float2(C[mt][nt][0], C[mt][nt][1]);
                if (aid1 >= 0)
                    *reinterpret_cast<float2*>(g_flat_d + aid1 * DIN + col) =
                        make_float2(C[mt][nt][2], C[mt][nt][3]);
            }
        }
    }
}

// ---------------- sparse force scatter ----------------
__global__ void k_scatter(const int* __restrict__ rows,
                          const int* __restrict__ cols,
                          const float* __restrict__ vals,
                          float* __restrict__ forces, int nnz)
{
    int t = blockIdx.x * blockDim.x + threadIdx.x;
    if (t < nnz) {
        float v = __ldg(vals + t) * g_flat_d[__ldg(rows + t)];
        atomicAdd(forces + __ldg(cols + t), -v);
    }
}

// ---------------- launch ----------------
extern "C" void kernel_launch(void* const* d_in, const int* in_sizes, int n_in,
                              void* d_out, int out_size)
{
    const int*   z    = (const int*)  d_in[0];
    const float* fp   = (const float*)d_in[1];
    const int*   img  = (const int*)  d_in[2];
    const int*   rows = (const int*)  d_in[3];
    const int*   cols = (const int*)  d_in[4];
    const float* vals = (const float*)d_in[5];
    int base = (in_sizes[6] == 3 * DIN * HID) ? 6 : 7;
    const float* W1 = (const float*)d_in[base + 0];
    const float* b1 = (const float*)d_in[base + 1];
    const float* W2 = (const float*)d_in[base + 2];
    const float* b2 = (const float*)d_in[base + 3];
    const float* W3 = (const float*)d_in[base + 4];
    const float* b3 = (const float*)d_in[base + 5];
    const float* W4 = (const float*)d_in[base + 6];
    const float* b4 = (const float*)d_in[base + 7];

    float* out    = (float*)d_out;
    float* energy = out;
    float* forces = out + NMOL;
    int nnz = in_sizes[3];

    cudaFuncSetAttribute(k_mlp, cudaFuncAttributeMaxDynamicSharedMemorySize, SMEM_DYN);

    int tot = NMOL + 3 * N_ATOMS;
    k_init   <<<(tot + 255) / 256, 256>>>(out);
    k_count  <<<(N_ATOMS + 255) / 256, 256>>>(z);
    k_offsets<<<1, 1>>>();
    k_build  <<<(N_ATOMS + 255) / 256, 256>>>(z);
    k_mlp    <<<NBLK, NTHR, SMEM_DYN>>>(z, fp, img, W1, b1, W2, b2, W3, b3, W4, b4, energy);
    k_scatter<<<(nnz + 255) / 256, 256>>>(rows, cols, vals, forces, nnz);
}

// round 5
// speedup vs baseline: 1.2784x; 1.2784x over previous
#include <cuda_runtime.h>
#include <cstdint>

// ---------------- problem constants ----------------
#define N_ATOMS 100000
#define DIN     120
#define HID     128
#define NMOL    2000
#define TILE    64                  // atoms per CTA
#define NTHR    128                 // 4 warps
#define NBLK    1566                // ceil((100000 + 3*63)/64)
#define PTOT    (NBLK * TILE)
#define LW      130                 // smem row stride (floats): conflict-free LDS.64

typedef unsigned long long ull;

// ---------------- device scratch ----------------
__device__ float g_flat_d[N_ATOMS * DIN];
__device__ int   perm_d[PTOT];
__device__ int   counts_d[3];
__device__ int   cursor_d[3];

__device__ __forceinline__ int elem_of(int z) {
    return (z == 1) ? 0 : ((z == 6) ? 1 : 2);
}

__device__ __forceinline__ float lo32(ull v) { return __uint_as_float((uint32_t)v); }
__device__ __forceinline__ float hi32(ull v) { return __uint_as_float((uint32_t)(v >> 32)); }

__device__ __forceinline__ float fast_tanh(float x) {
    x = fminf(15.f, fmaxf(-15.f, x));
    float e = __expf(2.f * x);
    return __fdividef(e - 1.f, e + 1.f);
}

// ---------------- prelude kernels ----------------
__global__ void k_init(float* __restrict__ out) {
    int i = blockIdx.x * blockDim.x + threadIdx.x;
    if (i < NMOL + 3 * N_ATOMS) out[i] = 0.f;
    if (i < PTOT) perm_d[i] = -1;
    if (i < 3) { counts_d[i] = 0; cursor_d[i] = 0; }
}

__global__ void k_count(const int* __restrict__ z) {
    __shared__ int loc[3];
    int t = threadIdx.x;
    if (t < 3) loc[t] = 0;
    __syncthreads();
    int i = blockIdx.x * blockDim.x + t;
    if (i < N_ATOMS) atomicAdd(&loc[elem_of(z[i])], 1);
    __syncthreads();
    if (t < 3 && loc[t] > 0) atomicAdd(&counts_d[t], loc[t]);
}

__global__ void k_offsets() {
    int r0 = (counts_d[0] + TILE - 1) / TILE * TILE;
    int r1 = (counts_d[1] + TILE - 1) / TILE * TILE;
    cursor_d[0] = 0;
    cursor_d[1] = r0;
    cursor_d[2] = r0 + r1;
}

__global__ void k_build(const int* __restrict__ z) {
    __shared__ int loc[3], base[3];
    int t = threadIdx.x;
    if (t < 3) loc[t] = 0;
    __syncthreads();
    int i = blockIdx.x * blockDim.x + t;
    int e = -1, r = 0;
    if (i < N_ATOMS) { e = elem_of(z[i]); r = atomicAdd(&loc[e], 1); }
    __syncthreads();
    if (t < 3) base[t] = (loc[t] > 0) ? atomicAdd(&cursor_d[t], loc[t]) : 0;
    __syncthreads();
    if (i < N_ATOMS) {
        int p = base[e] + r;
        if (p >= 0 && p < PTOT) perm_d[p] = i;
    }
}

// ---------------- weight staging (k contiguous in smem rows) ----------------
// Forward: WB[c][k] = W[k][c]  (transpose). Zeros for k >= Krows.
__device__ __forceinline__ void stage_wT(float* __restrict__ WB,
                                         const float* __restrict__ W,
                                         int Krows, int tid) {
    for (int i = tid; i < 4096; i += NTHR) {
        int c = i & 127, k = (i >> 7) * 4;        // k in 0,4,...,124
        float v0 = (k + 0 < Krows) ? __ldg(W + (k + 0) * HID + c) : 0.f;
        float v1 = (k + 1 < Krows) ? __ldg(W + (k + 1) * HID + c) : 0.f;
        float v2 = (k + 2 < Krows) ? __ldg(W + (k + 2) * HID + c) : 0.f;
        float v3 = (k + 3 < Krows) ? __ldg(W + (k + 3) * HID + c) : 0.f;
        float* p = WB + c * LW + k;
        p[0] = v0; p[1] = v1; p[2] = v2; p[3] = v3;
    }
}
// Backward: WB[m][k] = W[m][k] (native, k contiguous already).
__device__ __forceinline__ void stage_wN(float* __restrict__ WB,
                                         const float* __restrict__ W, int tid) {
    for (int i = tid; i < 4096; i += NTHR) {
        int m = i >> 5, k = (i & 31) * 4;
        float4 v = __ldg(reinterpret_cast<const float4*>(W + m * HID + k));
        float* p = WB + m * LW + k;
        p[0] = v.x; p[1] = v.y; p[2] = v.z; p[3] = v.w;
    }
}

// ---------------- packed-K f32x2 GEMM core ----------------
// acc[ai][ci] accumulates atom (arow0+ai) x col (cgi+16*ci), pair-summed over k.
__device__ __forceinline__ void gemm_f32x2(
    const float* __restrict__ As, const float* __restrict__ Bs,
    int arow0, int cgi, ull acc[8][8])
{
#pragma unroll
    for (int ai = 0; ai < 8; ai++)
#pragma unroll
        for (int ci = 0; ci < 8; ci++) acc[ai][ci] = 0ull;

    for (int kk = 0; kk < 64; kk++) {
        int k2 = kk * 2;
        ull wv[8], xv[8];
#pragma unroll
        for (int ci = 0; ci < 8; ci++)
            wv[ci] = *reinterpret_cast<const ull*>(Bs + (cgi + 16 * ci) * LW + k2);
#pragma unroll
        for (int ai = 0; ai < 8; ai++)
            xv[ai] = *reinterpret_cast<const ull*>(As + (arow0 + ai) * LW + k2);
#pragma unroll
        for (int ai = 0; ai < 8; ai++)
#pragma unroll
            for (int ci = 0; ci < 8; ci++)
                asm("fma.rn.f32x2 %0, %1, %2, %0;"
                    : "+l"(acc[ai][ci]) : "l"(xv[ai]), "l"(wv[ci]));
    }
}

// ---------------- fused MLP fwd+bwd (fp32, FFMA2) ----------------
// dyn smem: B0[64*130] | B1[64*130] | B2[64*130] | WB[128*130]
#define SMEM_DYN ((3 * TILE * LW + HID * LW) * 4)

__global__ __launch_bounds__(NTHR) void k_mlp(
    const int* __restrict__ z, const float* __restrict__ fp,
    const int* __restrict__ img,
    const float* __restrict__ W1, const float* __restrict__ b1,
    const float* __restrict__ W2, const float* __restrict__ b2,
    const float* __restrict__ W3, const float* __restrict__ b3,
    const float* __restrict__ W4, const float* __restrict__ b4,
    float* __restrict__ energy)
{
    extern __shared__ float sm[];
    float* B0 = sm;                    // X -> dp3
    float* B1 = B0 + TILE * LW;        // h1 -> dp1
    float* B2 = B1 + TILE * LW;        // h2 -> dp2
    float* WB = B2 + TILE * LW;        // staged weights [128][LW]

    __shared__ int s_aid[TILE];
    __shared__ int s_e;

    int tid = threadIdx.x;
    int cgi = tid & 15;                // col group (16)
    int rg  = tid >> 4;                // row group (8)
    int arow0 = rg * 8;

    if (tid == 0) s_e = -1;
    __syncthreads();
    if (tid < TILE) {
        int a = perm_d[blockIdx.x * TILE + tid];
        s_aid[tid] = a;
        if (a >= 0) s_e = elem_of(__ldg(z + a));
    }
    __syncthreads();
    if (s_e < 0) return;
    int e = s_e;

    const float* W1e = W1 + e * DIN * HID;
    const float* W2e = W2 + e * HID * HID;
    const float* W3e = W3 + e * HID * HID;
    const float* W4e = W4 + e * HID;
    const float* b1e = b1 + e * HID;
    const float* b2e = b2 + e * HID;
    const float* b3e = b3 + e * HID;
    float        b4e = __ldg(b4 + e);

    // stage X (zero-padded to 128 cols) and W1^T
    for (int i = tid; i < 2048; i += NTHR) {
        int a = i >> 5, k = (i & 31) * 4;
        int aid = s_aid[a];
        float4 v = make_float4(0.f, 0.f, 0.f, 0.f);
        if (aid >= 0 && k < DIN)
            v = __ldg(reinterpret_cast<const float4*>(fp + aid * DIN + k));
        float* p = B0 + a * LW + k;
        p[0] = v.x; p[1] = v.y; p[2] = v.z; p[3] = v.w;
    }
    stage_wT(WB, W1e, DIN, tid);
    __syncthreads();

    ull acc[8][8];

    // ======== Pass 1: h1 = tanh(X @ W1 + b1) -> B1 ========
    gemm_f32x2(B0, WB, arow0, cgi, acc);
#pragma unroll
    for (int ci = 0; ci < 8; ci++) {
        int col = cgi + 16 * ci;
        float bb = __ldg(b1e + col);
#pragma unroll
        for (int ai = 0; ai < 8; ai++)
            B1[(arow0 + ai) * LW + col] =
                fast_tanh(lo32(acc[ai][ci]) + hi32(acc[ai][ci]) + bb);
    }
    __syncthreads();
    stage_wT(WB, W2e, HID, tid);
    __syncthreads();

    // ======== Pass 2: h2 = tanh(h1 @ W2 + b2) -> B2 ========
    gemm_f32x2(B1, WB, arow0, cgi, acc);
#pragma unroll
    for (int ci = 0; ci < 8; ci++) {
        int col = cgi + 16 * ci;
        float bb = __ldg(b2e + col);
#pragma unroll
        for (int ai = 0; ai < 8; ai++)
            B2[(arow0 + ai) * LW + col] =
                fast_tanh(lo32(acc[ai][ci]) + hi32(acc[ai][ci]) + bb);
    }
    __syncthreads();
    stage_wT(WB, W3e, HID, tid);
    __syncthreads();

    // ======== Pass 3: h3 = tanh(h2 @ W3 + b3); energy; dp3 -> B0 ========
    gemm_f32x2(B2, WB, arow0, cgi, acc);
    {
        float ea[8];
#pragma unroll
        for (int ai = 0; ai < 8; ai++) ea[ai] = 0.f;
#pragma unroll
        for (int ci = 0; ci < 8; ci++) {
            int col = cgi + 16 * ci;
            float bb = __ldg(b3e + col);
            float w4 = __ldg(W4e + col);
#pragma unroll
            for (int ai = 0; ai < 8; ai++) {
                float h = fast_tanh(lo32(acc[ai][ci]) + hi32(acc[ai][ci]) + bb);
                ea[ai] += h * w4;
                B0[(arow0 + ai) * LW + col] = w4 * (1.f - h * h);
            }
        }
        // reduce over the 16 cgi lanes in each half-warp
#pragma unroll
        for (int ai = 0; ai < 8; ai++) {
            float v = ea[ai];
#pragma unroll
            for (int o = 1; o < 16; o <<= 1)
                v += __shfl_xor_sync(0xffffffffu, v, o);
            if (cgi == 0) {
                int aid = s_aid[arow0 + ai];
                if (aid >= 0)
                    atomicAdd(&energy[__ldg(img + aid)], v + b4e);
            }
        }
    }
    __syncthreads();
    stage_wN(WB, W3e, tid);          // backward: native W3
    __syncthreads();

    // ======== Pass 4: dp2 = (dp3 @ W3^T) * (1 - h2^2), in-place B2 ========
    gemm_f32x2(B0, WB, arow0, cgi, acc);
#pragma unroll
    for (int ci = 0; ci < 8; ci++) {
        int col = cgi + 16 * ci;
#pragma unroll
        for (int ai = 0; ai < 8; ai++) {
            float* p = B2 + (arow0 + ai) * LW + col;
            float h = *p;
            *p = (lo32(acc[ai][ci]) + hi32(acc[ai][ci])) * (1.f - h * h);
        }
    }
    __syncthreads();
    stage_wN(WB, W2e, tid);
    __syncthreads();

    // ======== Pass 5: dp1 = (dp2 @ W2^T) * (1 - h1^2), in-place B1 ========
    gemm_f32x2(B2, WB, arow0, cgi, acc);
#pragma unroll
    for (int ci = 0; ci < 8; ci++) {
        int col = cgi + 16 * ci;
#pragma unroll
        for (int ai = 0; ai < 8; ai++) {
            float* p = B1 + (arow0 + ai) * LW + col;
            float h = *p;
            *p = (lo32(acc[ai][ci]) + hi32(acc[ai][ci])) * (1.f - h * h);
        }
    }
    __syncthreads();
    stage_wN(WB, W1e, tid);          // rows m >= 120 unused (not stored)
    __syncthreads();

    // ======== Pass 6: g = dp1 @ W1^T (cols 0..119) -> global ========
    gemm_f32x2(B1, WB, arow0, cgi, acc);
#pragma unroll
    for (int ai = 0; ai < 8; ai++) {
        int aid = s_aid[arow0 + ai];
        if (aid < 0) continue;
        float* gp = g_flat_d + aid * DIN;
#pragma unroll
        for (int ci = 0; ci < 8; ci++) {
            int col = cgi + 16 * ci;
            if (col < DIN)
                gp[col] = lo32(acc[ai][ci]) + hi32(acc[ai][ci]);
        }
    }
}

// ---------------- sparse force scatter (4-wide) ----------------
__global__ void k_scatter(const int4* __restrict__ rows4,
                          const int4* __restrict__ cols4,
                          const float4* __restrict__ vals4,
                          const int* __restrict__ rows,
                          const int* __restrict__ cols,
                          const float* __restrict__ vals,
                          float* __restrict__ forces, int nnz)
{
    int n4 = nnz >> 2;
    int t = blockIdx.x * blockDim.x + threadIdx.x;
    if (t < n4) {
        int4   r = __ldg(rows4 + t);
        int4   c = __ldg(cols4 + t);
        float4 v = __ldg(vals4 + t);
        atomicAdd(forces + c.x, -v.x * g_flat_d[r.x]);
        atomicAdd(forces + c.y, -v.y * g_flat_d[r.y]);
        atomicAdd(forces + c.z, -v.z * g_flat_d[r.z]);
        atomicAdd(forces + c.w, -v.w * g_flat_d[r.w]);
    }
    if (t == 0) {
        for (int i = n4 << 2; i < nnz; i++)
            atomicAdd(forces + __ldg(cols + i), -__ldg(vals + i) * g_flat_d[__ldg(rows + i)]);
    }
}

// ---------------- launch ----------------
extern "C" void kernel_launch(void* const* d_in, const int* in_sizes, int n_in,
                              void* d_out, int out_size)
{
    const int*   z    = (const int*)  d_in[0];
    const float* fp   = (const float*)d_in[1];
    const int*   img  = (const int*)  d_in[2];
    const int*   rows = (const int*)  d_in[3];
    const int*   cols = (const int*)  d_in[4];
    const float* vals = (const float*)d_in[5];
    int base = (in_sizes[6] == 3 * DIN * HID) ? 6 : 7;
    const float* W1 = (const float*)d_in[base + 0];
    const float* b1 = (const float*)d_in[base + 1];
    const float* W2 = (const float*)d_in[base + 2];
    const float* b2 = (const float*)d_in[base + 3];
    const float* W3 = (const float*)d_in[base + 4];
    const float* b3 = (const float*)d_in[base + 5];
    const float* W4 = (const float*)d_in[base + 6];
    const float* b4 = (const float*)d_in[base + 7];

    float* out    = (float*)d_out;
    float* energy = out;
    float* forces = out + NMOL;
    int nnz = in_sizes[3];

    cudaFuncSetAttribute(k_mlp, cudaFuncAttributeMaxDynamicSharedMemorySize, SMEM_DYN);

    int tot = NMOL + 3 * N_ATOMS;
    k_init   <<<(tot + 255) / 256, 256>>>(out);
    k_count  <<<(N_ATOMS + 255) / 256, 256>>>(z);
    k_offsets<<<1, 1>>>();
    k_build  <<<(N_ATOMS + 255) / 256, 256>>>(z);
    k_mlp    <<<NBLK, NTHR, SMEM_DYN>>>(z, fp, img, W1, b1, W2, b2, W3, b3, W4, b4, energy);
    k_scatter<<<((nnz >> 2) + 255) / 256, 256>>>(
        (const int4*)rows, (const int4*)cols, (const float4*)vals,
        rows, cols, vals, forces, nnz);
}

// round 6
// speedup vs baseline: 1.3416x; 1.0494x over previous
#include <cuda_runtime.h>
#include <cstdint>

// ---------------- problem constants ----------------
#define N_ATOMS 100000
#define DIN     120
#define HID     128
#define NMOL    2000
#define TILE    64                  // atoms per CTA
#define NTHR    256                 // 8 warps (2 per SMSP)
#define NBLK    1566                // ceil((100000 + 3*63)/64)
#define PTOT    (NBLK * TILE)
#define LW      132                 // A rows [atom][k] stride
#define LWC     132                 // B rows [k][col] stride

// ---------------- device scratch ----------------
__device__ float g_flat_d[N_ATOMS * DIN];
__device__ int   perm_d[PTOT];
__device__ int   counts_d[3];
__device__ int   cursor_d[3];

__device__ __forceinline__ int elem_of(int z) {
    return (z == 1) ? 0 : ((z == 6) ? 1 : 2);
}

__device__ __forceinline__ float fast_tanh(float x) {
    x = fminf(15.f, fmaxf(-15.f, x));
    float e = __expf(2.f * x);
    return __fdividef(e - 1.f, e + 1.f);
}

// ---------------- prelude kernels (3 launches before k_mlp) ----------------
__global__ void k_init(float* __restrict__ out) {
    int i = blockIdx.x * blockDim.x + threadIdx.x;
    if (i < NMOL + 3 * N_ATOMS) out[i] = 0.f;
    if (i < PTOT) perm_d[i] = -1;
    if (i < 3) { counts_d[i] = 0; cursor_d[i] = 0; }
}

__global__ void k_count(const int* __restrict__ z) {
    __shared__ int loc[3];
    int t = threadIdx.x;
    if (t < 3) loc[t] = 0;
    __syncthreads();
    int i = blockIdx.x * blockDim.x + t;
    if (i < N_ATOMS) atomicAdd(&loc[elem_of(z[i])], 1);
    __syncthreads();
    if (t < 3 && loc[t] > 0) atomicAdd(&counts_d[t], loc[t]);
}

// offsets folded in: each block derives element bases from counts_d
__global__ void k_build(const int* __restrict__ z) {
    __shared__ int loc[3], base[3];
    int t = threadIdx.x;
    if (t < 3) loc[t] = 0;
    __syncthreads();
    int i = blockIdx.x * blockDim.x + t;
    int e = -1, r = 0;
    if (i < N_ATOMS) { e = elem_of(z[i]); r = atomicAdd(&loc[e], 1); }
    __syncthreads();
    if (t < 3) base[t] = (loc[t] > 0) ? atomicAdd(&cursor_d[t], loc[t]) : 0;
    __syncthreads();
    if (i < N_ATOMS) {
        int r0 = (counts_d[0] + TILE - 1) / TILE * TILE;
        int r1 = (counts_d[1] + TILE - 1) / TILE * TILE;
        int eb = (e == 0) ? 0 : ((e == 1) ? r0 : r0 + r1);
        int p = eb + base[e] + r;
        if (p >= 0 && p < PTOT) perm_d[p] = i;
    }
}

// ---------------- weight staging ----------------
// Forward: WB[k][c] = W[k][c]  (native copy, zero-pad k >= Krows)
__device__ __forceinline__ void stage_fwd(float* __restrict__ WB,
                                          const float* __restrict__ W,
                                          int Krows, int tid) {
    for (int idx = tid; idx < 4096; idx += NTHR) {
        int k = idx >> 5, c = (idx & 31) * 4;
        float4 v = make_float4(0.f, 0.f, 0.f, 0.f);
        if (k < Krows)
            v = __ldg(reinterpret_cast<const float4*>(W + k * HID + c));
        *reinterpret_cast<float4*>(WB + k * LWC + c) = v;
    }
}
// Backward: WB[k][m] = W[m][k]  (transpose; zero-pad m >= Mrows)
__device__ __forceinline__ void stage_bwd(float* __restrict__ WB,
                                          const float* __restrict__ W,
                                          int Mrows, int tid) {
    for (int idx = tid; idx < 4096; idx += NTHR) {
        int m = idx & 127, k = (idx >> 7) * 4;
        float4 v = make_float4(0.f, 0.f, 0.f, 0.f);
        if (m < Mrows)
            v = __ldg(reinterpret_cast<const float4*>(W + m * HID + k));
        WB[(k + 0) * LWC + m] = v.x;
        WB[(k + 1) * LWC + m] = v.y;
        WB[(k + 2) * LWC + m] = v.z;
        WB[(k + 3) * LWC + m] = v.w;
    }
}

// ---------------- FFMA GEMM core: thread = 8 atoms x 4 cols ----------------
__device__ __forceinline__ void gemm(
    const float* __restrict__ As, const float* __restrict__ Bs,
    int K4, int arow0, int c0, float acc[8][4])
{
#pragma unroll
    for (int ai = 0; ai < 8; ai++)
#pragma unroll
        for (int ci = 0; ci < 4; ci++) acc[ai][ci] = 0.f;

#pragma unroll 2
    for (int k4 = 0; k4 < K4; k4++) {
        int k = k4 * 4;
        float4 wv0 = *reinterpret_cast<const float4*>(Bs + (k + 0) * LWC + c0);
        float4 wv1 = *reinterpret_cast<const float4*>(Bs + (k + 1) * LWC + c0);
        float4 wv2 = *reinterpret_cast<const float4*>(Bs + (k + 2) * LWC + c0);
        float4 wv3 = *reinterpret_cast<const float4*>(Bs + (k + 3) * LWC + c0);
#pragma unroll
        for (int ai = 0; ai < 8; ai++) {
            float4 x = *reinterpret_cast<const float4*>(As + (arow0 + ai) * LW + k);
            acc[ai][0] = fmaf(x.x, wv0.x, acc[ai][0]);
            acc[ai][1] = fmaf(x.x, wv0.y, acc[ai][1]);
            acc[ai][2] = fmaf(x.x, wv0.z, acc[ai][2]);
            acc[ai][3] = fmaf(x.x, wv0.w, acc[ai][3]);
            acc[ai][0] = fmaf(x.y, wv1.x, acc[ai][0]);
            acc[ai][1] = fmaf(x.y, wv1.y, acc[ai][1]);
            acc[ai][2] = fmaf(x.y, wv1.z, acc[ai][2]);
            acc[ai][3] = fmaf(x.y, wv1.w, acc[ai][3]);
            acc[ai][0] = fmaf(x.z, wv2.x, acc[ai][0]);
            acc[ai][1] = fmaf(x.z, wv2.y, acc[ai][1]);
            acc[ai][2] = fmaf(x.z, wv2.z, acc[ai][2]);
            acc[ai][3] = fmaf(x.z, wv2.w, acc[ai][3]);
            acc[ai][0] = fmaf(x.w, wv3.x, acc[ai][0]);
            acc[ai][1] = fmaf(x.w, wv3.y, acc[ai][1]);
            acc[ai][2] = fmaf(x.w, wv3.z, acc[ai][2]);
            acc[ai][3] = fmaf(x.w, wv3.w, acc[ai][3]);
        }
    }
}

// ---------------- fused MLP fwd+bwd ----------------
// dyn smem: B0[64*132] | B1[64*132] | B2[64*132] | WB[128*132]   (~165 KB)
#define SMEM_DYN ((3 * TILE * LW + HID * LWC) * 4)

__global__ __launch_bounds__(NTHR) void k_mlp(
    const int* __restrict__ z, const float* __restrict__ fp,
    const int* __restrict__ img,
    const float* __restrict__ W1, const float* __restrict__ b1,
    const float* __restrict__ W2, const float* __restrict__ b2,
    const float* __restrict__ W3, const float* __restrict__ b3,
    const float* __restrict__ W4, const float* __restrict__ b4,
    float* __restrict__ energy)
{
    extern __shared__ float sm[];
    float* B0 = sm;                    // X -> dp3
    float* B1 = B0 + TILE * LW;        // h1 -> dp1
    float* B2 = B1 + TILE * LW;        // h2 -> dp2
    float* WB = B2 + TILE * LW;        // weights, K-major [k][col]

    __shared__ int s_aid[TILE];
    __shared__ int s_e;

    int tid = threadIdx.x;
    int wid = tid >> 5, lane = tid & 31;
    int arow0 = wid * 8;               // warp owns 8 atoms
    int c0 = lane * 4;                 // lane owns 4 cols

    if (tid == 0) s_e = -1;
    __syncthreads();
    if (tid < TILE) {
        int a = perm_d[blockIdx.x * TILE + tid];
        s_aid[tid] = a;
        if (a >= 0) s_e = elem_of(__ldg(z + a));
    }
    __syncthreads();
    if (s_e < 0) return;
    int e = s_e;

    const float* W1e = W1 + e * DIN * HID;
    const float* W2e = W2 + e * HID * HID;
    const float* W3e = W3 + e * HID * HID;
    const float* W4e = W4 + e * HID;
    const float* b1e = b1 + e * HID;
    const float* b2e = b2 + e * HID;
    const float* b3e = b3 + e * HID;
    float        b4e = __ldg(b4 + e);

    // stage X [atom][k] (zero-padded) and W1 forward
    for (int idx = tid; idx < 2048; idx += NTHR) {
        int a = idx >> 5, k = (idx & 31) * 4;
        int aid = s_aid[a];
        float4 v = make_float4(0.f, 0.f, 0.f, 0.f);
        if (aid >= 0 && k < DIN)
            v = __ldg(reinterpret_cast<const float4*>(fp + aid * DIN + k));
        *reinterpret_cast<float4*>(B0 + a * LW + k) = v;
    }
    stage_fwd(WB, W1e, DIN, tid);
    __syncthreads();

    float acc[8][4];

    // ======== Pass 1: h1 = tanh(X @ W1 + b1) -> B1  (K=120) ========
    gemm(B0, WB, 30, arow0, c0, acc);
    __syncthreads();
    {
        float4 bb = __ldg(reinterpret_cast<const float4*>(b1e + c0));
#pragma unroll
        for (int ai = 0; ai < 8; ai++) {
            float4 h;
            h.x = fast_tanh(acc[ai][0] + bb.x);
            h.y = fast_tanh(acc[ai][1] + bb.y);
            h.z = fast_tanh(acc[ai][2] + bb.z);
            h.w = fast_tanh(acc[ai][3] + bb.w);
            *reinterpret_cast<float4*>(B1 + (arow0 + ai) * LW + c0) = h;
        }
    }
    stage_fwd(WB, W2e, HID, tid);
    __syncthreads();

    // ======== Pass 2: h2 = tanh(h1 @ W2 + b2) -> B2 ========
    gemm(B1, WB, 32, arow0, c0, acc);
    __syncthreads();
    {
        float4 bb = __ldg(reinterpret_cast<const float4*>(b2e + c0));
#pragma unroll
        for (int ai = 0; ai < 8; ai++) {
            float4 h;
            h.x = fast_tanh(acc[ai][0] + bb.x);
            h.y = fast_tanh(acc[ai][1] + bb.y);
            h.z = fast_tanh(acc[ai][2] + bb.z);
            h.w = fast_tanh(acc[ai][3] + bb.w);
            *reinterpret_cast<float4*>(B2 + (arow0 + ai) * LW + c0) = h;
        }
    }
    stage_fwd(WB, W3e, HID, tid);
    __syncthreads();

    // ======== Pass 3: h3; energy; dp3 = W4*(1-h3^2) -> B0 ========
    gemm(B2, WB, 32, arow0, c0, acc);
    __syncthreads();
    {
        float4 bb = __ldg(reinterpret_cast<const float4*>(b3e + c0));
        float4 w4 = __ldg(reinterpret_cast<const float4*>(W4e + c0));
        float ea[8];
#pragma unroll
        for (int ai = 0; ai < 8; ai++) {
            float4 d;
            float h;
            h = fast_tanh(acc[ai][0] + bb.x); d.x = w4.x * (1.f - h * h);
            float p = h * w4.x;
            h = fast_tanh(acc[ai][1] + bb.y); d.y = w4.y * (1.f - h * h);
            p = fmaf(h, w4.y, p);
            h = fast_tanh(acc[ai][2] + bb.z); d.z = w4.z * (1.f - h * h);
            p = fmaf(h, w4.z, p);
            h = fast_tanh(acc[ai][3] + bb.w); d.w = w4.w * (1.f - h * h);
            p = fmaf(h, w4.w, p);
            ea[ai] = p;
            *reinterpret_cast<float4*>(B0 + (arow0 + ai) * LW + c0) = d;
        }
#pragma unroll
        for (int ai = 0; ai < 8; ai++) {
            float v = ea[ai];
#pragma unroll
            for (int o = 1; o < 32; o <<= 1)
                v += __shfl_xor_sync(0xffffffffu, v, o);
            if (lane == 0) {
                int aid = s_aid[arow0 + ai];
                if (aid >= 0)
                    atomicAdd(&energy[__ldg(img + aid)], v + b4e);
            }
        }
    }
    stage_bwd(WB, W3e, HID, tid);
    __syncthreads();

    // ======== Pass 4: dp2 = (dp3 @ W3^T) * (1 - h2^2), in-place B2 ========
    gemm(B0, WB, 32, arow0, c0, acc);
    __syncthreads();
#pragma unroll
    for (int ai = 0; ai < 8; ai++) {
        float4* p = reinterpret_cast<float4*>(B2 + (arow0 + ai) * LW + c0);
        float4 h = *p;
        h.x = acc[ai][0] * (1.f - h.x * h.x);
        h.y = acc[ai][1] * (1.f - h.y * h.y);
        h.z = acc[ai][2] * (1.f - h.z * h.z);
        h.w = acc[ai][3] * (1.f - h.w * h.w);
        *p = h;
    }
    stage_bwd(WB, W2e, HID, tid);
    __syncthreads();

    // ======== Pass 5: dp1 = (dp2 @ W2^T) * (1 - h1^2), in-place B1 ========
    gemm(B2, WB, 32, arow0, c0, acc);
    __syncthreads();
#pragma unroll
    for (int ai = 0; ai < 8; ai++) {
        float4* p = reinterpret_cast<float4*>(B1 + (arow0 + ai) * LW + c0);
        float4 h = *p;
        h.x = acc[ai][0] * (1.f - h.x * h.x);
        h.y = acc[ai][1] * (1.f - h.y * h.y);
        h.z = acc[ai][2] * (1.f - h.z * h.z);
        h.w = acc[ai][3] * (1.f - h.w * h.w);
        *p = h;
    }
    stage_bwd(WB, W1e, DIN, tid);     // cols m >= 120 staged as zero
    __syncthreads();

    // ======== Pass 6: g = dp1 @ W1^T -> global (cols 0..119) ========
    gemm(B1, WB, 32, arow0, c0, acc);
    if (c0 < DIN) {
#pragma unroll
        for (int ai = 0; ai < 8; ai++) {
            int aid = s_aid[arow0 + ai];
            if (aid >= 0)
                *reinterpret_cast<float4*>(g_flat_d + aid * DIN + c0) =
                    make_float4(acc[ai][0], acc[ai][1], acc[ai][2], acc[ai][3]);
        }
    }
}

// ---------------- sparse force scatter (4-wide) ----------------
__global__ void k_scatter(const int4* __restrict__ rows4,
                          const int4* __restrict__ cols4,
                          const float4* __restrict__ vals4,
                          const int* __restrict__ rows,
                          const int* __restrict__ cols,
                          const float* __restrict__ vals,
                          float* __restrict__ forces, int nnz)
{
    int n4 = nnz >> 2;
    int t = blockIdx.x * blockDim.x + threadIdx.x;
    if (t < n4) {
        int4   r = __ldg(rows4 + t);
        int4   c = __ldg(cols4 + t);
        float4 v = __ldg(vals4 + t);
        atomicAdd(forces + c.x, -v.x * g_flat_d[r.x]);
        atomicAdd(forces + c.y, -v.y * g_flat_d[r.y]);
        atomicAdd(forces + c.z, -v.z * g_flat_d[r.z]);
        atomicAdd(forces + c.w, -v.w * g_flat_d[r.w]);
    }
    if (t == 0) {
        for (int i = n4 << 2; i < nnz; i++)
            atomicAdd(forces + __ldg(cols + i),
                      -__ldg(vals + i) * g_flat_d[__ldg(rows + i)]);
    }
}

// ---------------- launch ----------------
extern "C" void kernel_launch(void* const* d_in, const int* in_sizes, int n_in,
                              void* d_out, int out_size)
{
    const int*   z    = (const int*)  d_in[0];
    const float* fp   = (const float*)d_in[1];
    const int*   img  = (const int*)  d_in[2];
    const int*   rows = (const int*)  d_in[3];
    const int*   cols = (const int*)  d_in[4];
    const float* vals = (const float*)d_in[5];
    int base = (in_sizes[6] == 3 * DIN * HID) ? 6 : 7;
    const float* W1 = (const float*)d_in[base + 0];
    const float* b1 = (const float*)d_in[base + 1];
    const float* W2 = (const float*)d_in[base + 2];
    const float* b2 = (const float*)d_in[base + 3];
    const float* W3 = (const float*)d_in[base + 4];
    const float* b3 = (const float*)d_in[base + 5];
    const float* W4 = (const float*)d_in[base + 6];
    const float* b4 = (const float*)d_in[base + 7];

    float* out    = (float*)d_out;
    float* energy = out;
    float* forces = out + NMOL;
    int nnz = in_sizes[3];

    cudaFuncSetAttribute(k_mlp, cudaFuncAttributeMaxDynamicSharedMemorySize, SMEM_DYN);

    int tot = NMOL + 3 * N_ATOMS;
    k_init   <<<(tot + 255) / 256, 256>>>(out);
    k_count  <<<(N_ATOMS + 255) / 256, 256>>>(z);
    k_build  <<<(N_ATOMS + 255) / 256, 256>>>(z);
    k_mlp    <<<NBLK, NTHR, SMEM_DYN>>>(z, fp, img, W1, b1, W2, b2, W3, b3, W4, b4, energy);
    k_scatter<<<((nnz >> 2) + 255) / 256, 256>>>(
        (const int4*)rows, (const int4*)cols, (const float4*)vals,
        rows, cols, vals, forces, nnz);
}